// round 11
// baseline (speedup 1.0000x reference)
#include <cuda_runtime.h>
#include <cstdint>

typedef unsigned long long ull;

__device__ __forceinline__ ull pack2(float lo, float hi) {
    ull r; asm("mov.b64 %0, {%1, %2};" : "=l"(r) : "f"(lo), "f"(hi)); return r;
}
__device__ __forceinline__ void unpack2(ull v, float& lo, float& hi) {
    asm("mov.b64 {%0, %1}, %2;" : "=f"(lo), "=f"(hi) : "l"(v));
}
#define FMA2(acc, a, b) asm("fma.rn.f32x2 %0, %1, %2, %0;" : "+l"(acc) : "l"(a), "l"(b))

__device__ __forceinline__ float tanh_approx(float x) {
    float y; asm("tanh.approx.f32 %0, %1;" : "=f"(y) : "f"(x)); return y;
}
__device__ __forceinline__ float sigf(float x) {           // final output only
    return __fdividef(1.f, 1.f + __expf(-x));
}

// In-quad 4x4 transpose: lane 4u+p enters with a[k] = its act for vec k,
// leaves with a[k] = gate-k act for vec p. Two xor-butterfly rounds.
__device__ __forceinline__ void quad_transpose(int p, float& a0, float& a1,
                                               float& a2, float& a3)
{
    float x0 = (p & 1) ? a0 : a1;
    float x1 = (p & 1) ? a2 : a3;
    x0 = __shfl_xor_sync(0xffffffffu, x0, 1);
    x1 = __shfl_xor_sync(0xffffffffu, x1, 1);
    if (p & 1) { a0 = x0; a2 = x1; } else { a1 = x0; a3 = x1; }
    float y0 = (p & 2) ? a0 : a2;
    float y1 = (p & 2) ? a1 : a3;
    y0 = __shfl_xor_sync(0xffffffffu, y0, 2);
    y1 = __shfl_xor_sync(0xffffffffu, y1, 2);
    if (p & 2) { a0 = y0; a1 = y1; } else { a2 = y0; a3 = y1; }
}

// P[v][slot], slot-permuted: slot 4u+p holds gate row p*64+u.  (51.2 MB)
__device__ float g_P[50000 * 256];

// ---------------------------------------------------------------------------
// Kernel 1: per-vocab input transform; writes permuted slots (R8 form).
// ---------------------------------------------------------------------------
__global__ __launch_bounds__(256)
void prep_kernel(const float* __restrict__ emb,
                 const float* __restrict__ w_ih0,
                 const float* __restrict__ b_ih0,
                 const float* __restrict__ b_hh0,
                 int V)
{
    const int E = 100;
    const int j = threadIdx.x;
    const int slot = 4 * (j & 63) + (j >> 6);

    ull w[50];
    {
        const ull* wp = reinterpret_cast<const ull*>(w_ih0 + (size_t)j * E);
#pragma unroll
        for (int k = 0; k < 50; k++) w[k] = wp[k];
    }
    const float bias = b_ih0[j] + b_hh0[j];

    __shared__ __align__(16) float es[4 * 100];

    for (int v0 = blockIdx.x * 4; v0 < V; v0 += gridDim.x * 4) {
        __syncthreads();
        int nload = min(4 * E, (V - v0) * E);
        for (int idx = j; idx < nload; idx += 256) es[idx] = emb[(size_t)v0 * E + idx];
        __syncthreads();

        ull acc0 = 0, acc1 = 0, acc2 = 0, acc3 = 0;
#pragma unroll
        for (int q = 0; q < 25; q++) {
            ulonglong2 h0 = *reinterpret_cast<const ulonglong2*>(&es[0 * 100 + q * 4]);
            ulonglong2 h1 = *reinterpret_cast<const ulonglong2*>(&es[1 * 100 + q * 4]);
            ulonglong2 h2 = *reinterpret_cast<const ulonglong2*>(&es[2 * 100 + q * 4]);
            ulonglong2 h3 = *reinterpret_cast<const ulonglong2*>(&es[3 * 100 + q * 4]);
            FMA2(acc0, w[2 * q], h0.x);  FMA2(acc0, w[2 * q + 1], h0.y);
            FMA2(acc1, w[2 * q], h1.x);  FMA2(acc1, w[2 * q + 1], h1.y);
            FMA2(acc2, w[2 * q], h2.x);  FMA2(acc2, w[2 * q + 1], h2.y);
            FMA2(acc3, w[2 * q], h3.x);  FMA2(acc3, w[2 * q + 1], h3.y);
        }
        ull accs[4] = {acc0, acc1, acc2, acc3};
#pragma unroll
        for (int r = 0; r < 4; r++) {
            if (v0 + r < V) {
                float lo, hi; unpack2(accs[r], lo, hi);
                g_P[(size_t)(v0 + r) * 256 + slot] = lo + hi + bias;
            }
        }
    }
}

// ---------------------------------------------------------------------------
// Kernel 2: fused 2-layer LSTM scan; layer-1 one step behind; peeled
// prologue/epilogue; branchless rolled interior; gate exchange via in-quad
// shuffle transpose (no sact smem, no __syncwarp); sentinel prefetch.
// Weights loaded as untouched 64-bit words (keeps ptxas pairing; R8 lesson).
// ---------------------------------------------------------------------------
__global__ __launch_bounds__(256, 1)
void scan_kernel(const int*   __restrict__ x,
                 const float* __restrict__ w_hh0,
                 const float* __restrict__ w_ih1,
                 const float* __restrict__ w_hh1,
                 const float* __restrict__ b_ih1,
                 const float* __restrict__ b_hh1,
                 const float* __restrict__ fc_w,
                 const float* __restrict__ fc_b,
                 float* __restrict__ out,
                 int T)
{
    const int HH = 64;
    const int t_ = threadIdx.x;
    const int p  = t_ & 3;        // gate type 0=i 1=f 2=g 3=o
    const int u  = t_ >> 2;       // unit 0..63
    const int r  = p * 64 + u;    // original gate row
    const int b0 = blockIdx.x * 2;
    const bool is_g = (p == 2);

    __shared__ __align__(16) float hs[2][4][68];     // [buf][vec][unit], padded
    __shared__ int sx[2][513];                       // +1 sentinel slot

    ull w0[32], wi[32], wh[32];
    {
        const ull* q0 = reinterpret_cast<const ull*>(w_hh0 + (size_t)r * HH);
        const ull* q1 = reinterpret_cast<const ull*>(w_ih1 + (size_t)r * HH);
        const ull* q2 = reinterpret_cast<const ull*>(w_hh1 + (size_t)r * HH);
#pragma unroll
        for (int k = 0; k < 32; k++) { w0[k] = q0[k]; wi[k] = q1[k]; wh[k] = q2[k]; }
    }
    const float bias1 = b_ih1[r] + b_hh1[r];

    for (int i = t_; i < T; i += 256) {
        sx[0][i] = x[(size_t)b0 * T + i];
        sx[1][i] = x[(size_t)(b0 + 1) * T + i];
    }
    if (t_ < 2) sx[t_][T] = 0;                       // sentinel
    for (int i = t_; i < 2 * 4 * 68; i += 256) ((float*)hs)[i] = 0.f;

    float cstate = 0.f;     // lane's cell state for its (layer,row) = vec p

    // act = 0.5*tanh(0.5*x)+0.5 for sigmoid gates; tanh(x) for the g gate.
    const float argscale = is_g ? 1.f : 0.5f;
    const float resmul   = is_g ? 1.f : 0.5f;
    const float resadd   = is_g ? 0.f : 0.5f;
    const int* sx0 = sx[0];
    const int* sx1 = sx[1];

    __syncthreads();

    float curP0 = g_P[(size_t)sx0[0] * 256 + t_];
    float curP1 = g_P[(size_t)sx1[0] * 256 + t_];

    // ================= prologue t = 0: layer0 only =================
    {
        float nP0 = g_P[(size_t)sx0[1] * 256 + t_];
        float nP1 = g_P[(size_t)sx1[1] * 256 + t_];
        float a0 = fmaf(tanh_approx(curP0 * argscale), resmul, resadd);
        float a1 = fmaf(tanh_approx(curP1 * argscale), resmul, resadd);
        float a2 = 0.f, a3 = 0.f;
        quad_transpose(p, a0, a1, a2, a3);
        if (p < 2) {
            cstate = a1 * cstate + a0 * a2;
            hs[1][p][u] = a3 * tanh_approx(cstate);
        }
        curP0 = nP0; curP1 = nP1;
        __syncthreads();
    }

    // ================= interior t = 1 .. T-1: rolled, branchless ==========
#pragma unroll 1
    for (int t = 1; t < T; t++) {
        int cur = t & 1, nxt = cur ^ 1;
        float nP0 = g_P[(size_t)sx0[t + 1] * 256 + t_];   // sentinel at t=T-1
        float nP1 = g_P[(size_t)sx1[t + 1] * 256 + t_];

        const float* H = &hs[cur][0][0];              // vec rows at stride 68

        ull a0  = pack2(curP0, 0.f);
        ull a1  = pack2(curP1, 0.f);
        ull g1a = pack2(bias1, 0.f);
        ull g1b = pack2(bias1, 0.f);
        ull g1c = 0ull;
        ull g1d = 0ull;
#pragma unroll
        for (int q = 0; q < 16; q++) {
            ulonglong2 u0 = *reinterpret_cast<const ulonglong2*>(H + 0 * 68 + q * 4);
            ulonglong2 u1 = *reinterpret_cast<const ulonglong2*>(H + 1 * 68 + q * 4);
            ulonglong2 v0 = *reinterpret_cast<const ulonglong2*>(H + 2 * 68 + q * 4);
            ulonglong2 v1 = *reinterpret_cast<const ulonglong2*>(H + 3 * 68 + q * 4);
            FMA2(a0,  w0[2 * q],     u0.x);
            FMA2(a1,  w0[2 * q],     u1.x);
            FMA2(g1a, wi[2 * q],     u0.x);
            FMA2(g1b, wi[2 * q],     u1.x);
            FMA2(g1c, wh[2 * q],     v0.x);
            FMA2(g1d, wh[2 * q],     v1.x);
            FMA2(a0,  w0[2 * q + 1], u0.y);
            FMA2(a1,  w0[2 * q + 1], u1.y);
            FMA2(g1a, wi[2 * q + 1], u0.y);
            FMA2(g1b, wi[2 * q + 1], u1.y);
            FMA2(g1c, wh[2 * q + 1], v0.y);
            FMA2(g1d, wh[2 * q + 1], v1.y);
        }
        {
            float lo, hi, lo2, hi2;
            unpack2(a0, lo, hi);  float s0 = lo + hi;
            unpack2(a1, lo, hi);  float s1 = lo + hi;
            unpack2(g1a, lo, hi); unpack2(g1c, lo2, hi2);
            float v0 = (lo + hi) + (lo2 + hi2);
            unpack2(g1b, lo, hi); unpack2(g1d, lo2, hi2);
            float v1 = (lo + hi) + (lo2 + hi2);
            float b0v = fmaf(tanh_approx(s0 * argscale), resmul, resadd);
            float b1v = fmaf(tanh_approx(s1 * argscale), resmul, resadd);
            float b2v = fmaf(tanh_approx(v0 * argscale), resmul, resadd);
            float b3v = fmaf(tanh_approx(v1 * argscale), resmul, resadd);
            quad_transpose(p, b0v, b1v, b2v, b3v);
            // b0v..b3v = (i, f, g, o) for this lane's vec p
            cstate = b1v * cstate + b0v * b2v;
            hs[nxt][p][u] = b3v * tanh_approx(cstate);
        }
        curP0 = nP0; curP1 = nP1;
        __syncthreads();
    }

    // ================= epilogue t = T: layer1 only =================
    {
        const float* H = &hs[T & 1][0][0];
        ull g1a = pack2(bias1, 0.f);
        ull g1b = pack2(bias1, 0.f);
        ull g1c = 0ull;
        ull g1d = 0ull;
#pragma unroll
        for (int q = 0; q < 16; q++) {
            ulonglong2 u0 = *reinterpret_cast<const ulonglong2*>(H + 0 * 68 + q * 4);
            ulonglong2 u1 = *reinterpret_cast<const ulonglong2*>(H + 1 * 68 + q * 4);
            ulonglong2 v0 = *reinterpret_cast<const ulonglong2*>(H + 2 * 68 + q * 4);
            ulonglong2 v1 = *reinterpret_cast<const ulonglong2*>(H + 3 * 68 + q * 4);
            FMA2(g1a, wi[2 * q],     u0.x);
            FMA2(g1b, wi[2 * q],     u1.x);
            FMA2(g1c, wh[2 * q],     v0.x);
            FMA2(g1d, wh[2 * q],     v1.x);
            FMA2(g1a, wi[2 * q + 1], u0.y);
            FMA2(g1b, wi[2 * q + 1], u1.y);
            FMA2(g1c, wh[2 * q + 1], v0.y);
            FMA2(g1d, wh[2 * q + 1], v1.y);
        }
        {
            float lo, hi, lo2, hi2;
            unpack2(g1a, lo, hi); unpack2(g1c, lo2, hi2);
            float v0 = (lo + hi) + (lo2 + hi2);
            unpack2(g1b, lo, hi); unpack2(g1d, lo2, hi2);
            float v1 = (lo + hi) + (lo2 + hi2);
            float a0 = 0.f, a1 = 0.f;
            float a2 = fmaf(tanh_approx(v0 * argscale), resmul, resadd);
            float a3 = fmaf(tanh_approx(v1 * argscale), resmul, resadd);
            quad_transpose(p, a0, a1, a2, a3);
            if (p >= 2) {
                cstate = a1 * cstate + a0 * a2;
                hs[1][p][u] = a3 * tanh_approx(cstate);   // h1(T-1)
            }
        }
        __syncthreads();
    }

    // ---- final: out[b] = sigmoid(relu(h1(T-1)) . fc_w + fc_b) ----
    if (t_ < 2) {
        const float* hf = &hs[1][2 + t_][0];
        float sacc = fc_b[0];
#pragma unroll
        for (int uu = 0; uu < HH; uu++)
            sacc += fmaxf(hf[uu], 0.f) * fc_w[uu];
        out[b0 + t_] = sigf(sacc);
    }
}

// ---------------------------------------------------------------------------
// Launch
// ---------------------------------------------------------------------------
extern "C" void kernel_launch(void* const* d_in, const int* in_sizes, int n_in,
                              void* d_out, int out_size)
{
    const int*   x     = (const int*)  d_in[0];
    const float* emb   = (const float*)d_in[1];
    const float* w_ih0 = (const float*)d_in[2];
    const float* w_hh0 = (const float*)d_in[3];
    const float* b_ih0 = (const float*)d_in[4];
    const float* b_hh0 = (const float*)d_in[5];
    const float* w_ih1 = (const float*)d_in[6];
    const float* w_hh1 = (const float*)d_in[7];
    const float* b_ih1 = (const float*)d_in[8];
    const float* b_hh1 = (const float*)d_in[9];
    const float* fc_w  = (const float*)d_in[10];
    const float* fc_b  = (const float*)d_in[11];
    float* out = (float*)d_out;

    const int B = out_size;              // 256
    const int T = in_sizes[0] / B;       // 512 (even)
    const int E = in_sizes[2] / 256;     // 100
    const int V = in_sizes[1] / E;       // 50000

    (void)n_in; (void)E;

    prep_kernel<<<296, 256>>>(emb, w_ih0, b_ih0, b_hh0, V);
    scan_kernel<<<B / 2, 256>>>(x, w_hh0, w_ih1, w_hh1, b_ih1, b_hh1,
                                fc_w, fc_b, out, T);
}

// round 12
// speedup vs baseline: 1.0692x; 1.0692x over previous
#include <cuda_runtime.h>
#include <cstdint>

typedef unsigned long long ull;

__device__ __forceinline__ ull pack2(float lo, float hi) {
    ull r; asm("mov.b64 %0, {%1, %2};" : "=l"(r) : "f"(lo), "f"(hi)); return r;
}
__device__ __forceinline__ void unpack2(ull v, float& lo, float& hi) {
    asm("mov.b64 {%0, %1}, %2;" : "=f"(lo), "=f"(hi) : "l"(v));
}
#define FMA2(acc, a, b) asm("fma.rn.f32x2 %0, %1, %2, %0;" : "+l"(acc) : "l"(a), "l"(b))

__device__ __forceinline__ float tanh_approx(float x) {
    float y; asm("tanh.approx.f32 %0, %1;" : "=f"(y) : "f"(x)); return y;
}
__device__ __forceinline__ float sigf(float x) {           // final output only
    return __fdividef(1.f, 1.f + __expf(-x));
}

// P[v][slot], slot-permuted: slot 4u+p holds gate row p*64+u.  (51.2 MB)
__device__ float g_P[50000 * 256];

// ---------------------------------------------------------------------------
// Kernel 1: per-vocab input transform; writes permuted slots (R8 form).
// ---------------------------------------------------------------------------
__global__ __launch_bounds__(256)
void prep_kernel(const float* __restrict__ emb,
                 const float* __restrict__ w_ih0,
                 const float* __restrict__ b_ih0,
                 const float* __restrict__ b_hh0,
                 int V)
{
    const int E = 100;
    const int j = threadIdx.x;
    const int slot = 4 * (j & 63) + (j >> 6);

    ull w[50];
    {
        const ull* wp = reinterpret_cast<const ull*>(w_ih0 + (size_t)j * E);
#pragma unroll
        for (int k = 0; k < 50; k++) w[k] = wp[k];
    }
    const float bias = b_ih0[j] + b_hh0[j];

    __shared__ __align__(16) float es[4 * 100];

    for (int v0 = blockIdx.x * 4; v0 < V; v0 += gridDim.x * 4) {
        __syncthreads();
        int nload = min(4 * E, (V - v0) * E);
        for (int idx = j; idx < nload; idx += 256) es[idx] = emb[(size_t)v0 * E + idx];
        __syncthreads();

        ull acc0 = 0, acc1 = 0, acc2 = 0, acc3 = 0;
#pragma unroll
        for (int q = 0; q < 25; q++) {
            ulonglong2 h0 = *reinterpret_cast<const ulonglong2*>(&es[0 * 100 + q * 4]);
            ulonglong2 h1 = *reinterpret_cast<const ulonglong2*>(&es[1 * 100 + q * 4]);
            ulonglong2 h2 = *reinterpret_cast<const ulonglong2*>(&es[2 * 100 + q * 4]);
            ulonglong2 h3 = *reinterpret_cast<const ulonglong2*>(&es[3 * 100 + q * 4]);
            FMA2(acc0, w[2 * q], h0.x);  FMA2(acc0, w[2 * q + 1], h0.y);
            FMA2(acc1, w[2 * q], h1.x);  FMA2(acc1, w[2 * q + 1], h1.y);
            FMA2(acc2, w[2 * q], h2.x);  FMA2(acc2, w[2 * q + 1], h2.y);
            FMA2(acc3, w[2 * q], h3.x);  FMA2(acc3, w[2 * q + 1], h3.y);
        }
        ull accs[4] = {acc0, acc1, acc2, acc3};
#pragma unroll
        for (int r = 0; r < 4; r++) {
            if (v0 + r < V) {
                float lo, hi; unpack2(accs[r], lo, hi);
                g_P[(size_t)(v0 + r) * 256 + slot] = lo + hi + bias;
            }
        }
    }
}

// ---------------------------------------------------------------------------
// Kernel 2: fused 2-layer LSTM scan (R8 structure exactly), plus sentinel
// token slot so the interior prefetch index is unconditionally t+1.
// Layer-1 pipelined one step behind; peeled prologue/epilogue; branchless
// rolled interior; quad-remapped gates; cells intra-warp via sact smem.
// Weights loaded as untouched 64-bit words (ptxas pairing; R10 lesson).
// ---------------------------------------------------------------------------
__global__ __launch_bounds__(256, 1)
void scan_kernel(const int*   __restrict__ x,
                 const float* __restrict__ w_hh0,
                 const float* __restrict__ w_ih1,
                 const float* __restrict__ w_hh1,
                 const float* __restrict__ b_ih1,
                 const float* __restrict__ b_hh1,
                 const float* __restrict__ fc_w,
                 const float* __restrict__ fc_b,
                 float* __restrict__ out,
                 int T)
{
    const int HH = 64;
    const int t_ = threadIdx.x;
    const int p  = t_ & 3;        // gate type 0=i 1=f 2=g 3=o
    const int u  = t_ >> 2;       // unit 0..63
    const int r  = p * 64 + u;    // original gate row
    const int b0 = blockIdx.x * 2;
    const bool is_g = (p == 2);

    __shared__ __align__(16) float hs[2][4][68];     // [buf][vec][unit], padded
    __shared__ __align__(16) float sact[4][260];     // [vec][slot 4u+p], padded
    __shared__ int sx[2][513];                       // +1 sentinel slot

    ull w0[32], wi[32], wh[32];
    {
        const ull* q0 = reinterpret_cast<const ull*>(w_hh0 + (size_t)r * HH);
        const ull* q1 = reinterpret_cast<const ull*>(w_ih1 + (size_t)r * HH);
        const ull* q2 = reinterpret_cast<const ull*>(w_hh1 + (size_t)r * HH);
#pragma unroll
        for (int k = 0; k < 32; k++) { w0[k] = q0[k]; wi[k] = q1[k]; wh[k] = q2[k]; }
    }
    const float bias1 = b_ih1[r] + b_hh1[r];

    for (int i = t_; i < T; i += 256) {
        sx[0][i] = x[(size_t)b0 * T + i];
        sx[1][i] = x[(size_t)(b0 + 1) * T + i];
    }
    if (t_ < 2) sx[t_][T] = 0;                       // sentinel
    for (int i = t_; i < 2 * 4 * 68; i += 256) ((float*)hs)[i] = 0.f;

    float cstate = 0.f;     // lane's cell state for its (layer,row) = vec p

    // act = 0.5*tanh(0.5*x)+0.5 for sigmoid gates; tanh(x) for the g gate.
    const float argscale = is_g ? 1.f : 0.5f;
    const float resmul   = is_g ? 1.f : 0.5f;
    const float resadd   = is_g ? 0.f : 0.5f;
    const float* csrc = &sact[p][4 * (unsigned)u];
    const int* sx0 = sx[0];
    const int* sx1 = sx[1];

    __syncthreads();

    float curP0 = g_P[(size_t)sx0[0] * 256 + t_];
    float curP1 = g_P[(size_t)sx1[0] * 256 + t_];

    // ================= prologue t = 0: layer0 only =================
    {
        float nP0 = g_P[(size_t)sx0[1] * 256 + t_];
        float nP1 = g_P[(size_t)sx1[1] * 256 + t_];
        sact[0][t_] = fmaf(tanh_approx(curP0 * argscale), resmul, resadd);
        sact[1][t_] = fmaf(tanh_approx(curP1 * argscale), resmul, resadd);
        __syncwarp();
        if (p < 2) {
            float4 g4 = *reinterpret_cast<const float4*>(csrc);
            cstate = g4.y * cstate + g4.x * g4.z;
            hs[1][p][u] = g4.w * tanh_approx(cstate);
        }
        curP0 = nP0; curP1 = nP1;
        __syncthreads();
    }

    // ================= interior t = 1 .. T-1: rolled, branchless ==========
#pragma unroll 1
    for (int t = 1; t < T; t++) {
        int cur = t & 1, nxt = cur ^ 1;
        float nP0 = g_P[(size_t)sx0[t + 1] * 256 + t_];   // sentinel at t=T-1
        float nP1 = g_P[(size_t)sx1[t + 1] * 256 + t_];

        const float* H = &hs[cur][0][0];              // vec rows at stride 68

        ull a0  = pack2(curP0, 0.f);
        ull a1  = pack2(curP1, 0.f);
        ull g1a = pack2(bias1, 0.f);
        ull g1b = pack2(bias1, 0.f);
        ull g1c = 0ull;
        ull g1d = 0ull;
#pragma unroll
        for (int q = 0; q < 16; q++) {
            ulonglong2 u0 = *reinterpret_cast<const ulonglong2*>(H + 0 * 68 + q * 4);
            ulonglong2 u1 = *reinterpret_cast<const ulonglong2*>(H + 1 * 68 + q * 4);
            ulonglong2 v0 = *reinterpret_cast<const ulonglong2*>(H + 2 * 68 + q * 4);
            ulonglong2 v1 = *reinterpret_cast<const ulonglong2*>(H + 3 * 68 + q * 4);
            FMA2(a0,  w0[2 * q],     u0.x);
            FMA2(a1,  w0[2 * q],     u1.x);
            FMA2(g1a, wi[2 * q],     u0.x);
            FMA2(g1b, wi[2 * q],     u1.x);
            FMA2(g1c, wh[2 * q],     v0.x);
            FMA2(g1d, wh[2 * q],     v1.x);
            FMA2(a0,  w0[2 * q + 1], u0.y);
            FMA2(a1,  w0[2 * q + 1], u1.y);
            FMA2(g1a, wi[2 * q + 1], u0.y);
            FMA2(g1b, wi[2 * q + 1], u1.y);
            FMA2(g1c, wh[2 * q + 1], v0.y);
            FMA2(g1d, wh[2 * q + 1], v1.y);
        }
        {
            float lo, hi, lo2, hi2;
            unpack2(a0, lo, hi);  float s0 = lo + hi;
            unpack2(a1, lo, hi);  float s1 = lo + hi;
            unpack2(g1a, lo, hi); unpack2(g1c, lo2, hi2);
            float v0 = (lo + hi) + (lo2 + hi2);
            unpack2(g1b, lo, hi); unpack2(g1d, lo2, hi2);
            float v1 = (lo + hi) + (lo2 + hi2);
            sact[0][t_] = fmaf(tanh_approx(s0 * argscale), resmul, resadd);
            sact[1][t_] = fmaf(tanh_approx(s1 * argscale), resmul, resadd);
            sact[2][t_] = fmaf(tanh_approx(v0 * argscale), resmul, resadd);
            sact[3][t_] = fmaf(tanh_approx(v1 * argscale), resmul, resadd);
        }
        __syncwarp();

        // branchless cell: every lane updates its vec p
        {
            float4 g4 = *reinterpret_cast<const float4*>(csrc);
            cstate = g4.y * cstate + g4.x * g4.z;
            hs[nxt][p][u] = g4.w * tanh_approx(cstate);
        }
        curP0 = nP0; curP1 = nP1;
        __syncthreads();
    }

    // ================= epilogue t = T: layer1 only =================
    {
        const float* H = &hs[T & 1][0][0];
        ull g1a = pack2(bias1, 0.f);
        ull g1b = pack2(bias1, 0.f);
        ull g1c = 0ull;
        ull g1d = 0ull;
#pragma unroll
        for (int q = 0; q < 16; q++) {
            ulonglong2 u0 = *reinterpret_cast<const ulonglong2*>(H + 0 * 68 + q * 4);
            ulonglong2 u1 = *reinterpret_cast<const ulonglong2*>(H + 1 * 68 + q * 4);
            ulonglong2 v0 = *reinterpret_cast<const ulonglong2*>(H + 2 * 68 + q * 4);
            ulonglong2 v1 = *reinterpret_cast<const ulonglong2*>(H + 3 * 68 + q * 4);
            FMA2(g1a, wi[2 * q],     u0.x);
            FMA2(g1b, wi[2 * q],     u1.x);
            FMA2(g1c, wh[2 * q],     v0.x);
            FMA2(g1d, wh[2 * q],     v1.x);
            FMA2(g1a, wi[2 * q + 1], u0.y);
            FMA2(g1b, wi[2 * q + 1], u1.y);
            FMA2(g1c, wh[2 * q + 1], v0.y);
            FMA2(g1d, wh[2 * q + 1], v1.y);
        }
        {
            float lo, hi, lo2, hi2;
            unpack2(g1a, lo, hi); unpack2(g1c, lo2, hi2);
            float v0 = (lo + hi) + (lo2 + hi2);
            unpack2(g1b, lo, hi); unpack2(g1d, lo2, hi2);
            float v1 = (lo + hi) + (lo2 + hi2);
            sact[2][t_] = fmaf(tanh_approx(v0 * argscale), resmul, resadd);
            sact[3][t_] = fmaf(tanh_approx(v1 * argscale), resmul, resadd);
        }
        __syncwarp();
        if (p >= 2) {
            float4 g4 = *reinterpret_cast<const float4*>(csrc);
            cstate = g4.y * cstate + g4.x * g4.z;
            hs[1][p][u] = g4.w * tanh_approx(cstate);   // h1(T-1), buf 1 (T even)
        }
        __syncthreads();
    }

    // ---- final: out[b] = sigmoid(relu(h1(T-1)) . fc_w + fc_b) ----
    if (t_ < 2) {
        const float* hf = &hs[1][2 + t_][0];
        float sacc = fc_b[0];
#pragma unroll
        for (int uu = 0; uu < HH; uu++)
            sacc += fmaxf(hf[uu], 0.f) * fc_w[uu];
        out[b0 + t_] = sigf(sacc);
    }
}

// ---------------------------------------------------------------------------
// Launch
// ---------------------------------------------------------------------------
extern "C" void kernel_launch(void* const* d_in, const int* in_sizes, int n_in,
                              void* d_out, int out_size)
{
    const int*   x     = (const int*)  d_in[0];
    const float* emb   = (const float*)d_in[1];
    const float* w_ih0 = (const float*)d_in[2];
    const float* w_hh0 = (const float*)d_in[3];
    const float* b_ih0 = (const float*)d_in[4];
    const float* b_hh0 = (const float*)d_in[5];
    const float* w_ih1 = (const float*)d_in[6];
    const float* w_hh1 = (const float*)d_in[7];
    const float* b_ih1 = (const float*)d_in[8];
    const float* b_hh1 = (const float*)d_in[9];
    const float* fc_w  = (const float*)d_in[10];
    const float* fc_b  = (const float*)d_in[11];
    float* out = (float*)d_out;

    const int B = out_size;              // 256
    const int T = in_sizes[0] / B;       // 512 (even)
    const int E = in_sizes[2] / 256;     // 100
    const int V = in_sizes[1] / E;       // 50000

    (void)n_in; (void)E;

    prep_kernel<<<296, 256>>>(emb, w_ih0, b_ih0, b_hh0, V);
    scan_kernel<<<B / 2, 256>>>(x, w_hh0, w_ih1, w_hh1, b_ih1, b_hh1,
                                fc_w, fc_b, out, T);
}

// round 13
// speedup vs baseline: 1.1607x; 1.0856x over previous
#include <cuda_runtime.h>
#include <cstdint>

typedef unsigned long long ull;

__device__ __forceinline__ ull pack2(float lo, float hi) {
    ull r; asm("mov.b64 %0, {%1, %2};" : "=l"(r) : "f"(lo), "f"(hi)); return r;
}
__device__ __forceinline__ void unpack2(ull v, float& lo, float& hi) {
    asm("mov.b64 {%0, %1}, %2;" : "=f"(lo), "=f"(hi) : "l"(v));
}
#define FMA2(acc, a, b) asm("fma.rn.f32x2 %0, %1, %2, %0;" : "+l"(acc) : "l"(a), "l"(b))

__device__ __forceinline__ float tanh_approx(float x) {
    float y; asm("tanh.approx.f32 %0, %1;" : "=f"(y) : "f"(x)); return y;
}
__device__ __forceinline__ float sigf(float x) {           // final output only
    return __fdividef(1.f, 1.f + __expf(-x));
}

// P[v][slot], slot-permuted: slot 4u+p holds gate row p*64+u.  (51.2 MB)
__device__ float g_P[50000 * 256];

// ---------------------------------------------------------------------------
// Kernel 1 (v2): per-vocab input transform, double-buffered smem staging.
// One barrier per 4-row chunk; next chunk's emb rows prefetched into
// registers while the current chunk's FMA2 block provides latency cover.
// ---------------------------------------------------------------------------
__global__ __launch_bounds__(256, 2)
void prep_kernel(const float* __restrict__ emb,
                 const float* __restrict__ w_ih0,
                 const float* __restrict__ b_ih0,
                 const float* __restrict__ b_hh0,
                 int V)
{
    const int E = 100;
    const int j = threadIdx.x;
    const int slot = 4 * (j & 63) + (j >> 6);

    ull w[50];
    {
        const ull* wp = reinterpret_cast<const ull*>(w_ih0 + (size_t)j * E);
#pragma unroll
        for (int k = 0; k < 50; k++) w[k] = wp[k];
    }
    const float bias = b_ih0[j] + b_hh0[j];

    __shared__ __align__(16) float es[2][400];

    const int nchunk = (V + 3) / 4;              // 12500 for V=50000
    int c = blockIdx.x;
    if (c >= nchunk) return;

    // prologue: stage chunk c into es[0]
    {
        const float* base = emb + (size_t)c * 400;
        es[0][j] = base[j];
        int j2 = j + 256;
        if (j2 < 400) es[0][j2] = base[j2];
    }
    __syncthreads();

    int buf = 0;
    for (; c < nchunk; c += gridDim.x) {
        int cn = c + gridDim.x;
        // prefetch next chunk into registers (LDG in flight across compute)
        float r0 = 0.f, r1 = 0.f;
        if (cn < nchunk) {
            const float* base = emb + (size_t)cn * 400;
            r0 = base[j];
            if (j + 256 < 400) r1 = base[j + 256];
        }

        const float* esb = es[buf];
        ull acc0 = 0, acc1 = 0, acc2 = 0, acc3 = 0;
#pragma unroll
        for (int q = 0; q < 25; q++) {
            ulonglong2 h0 = *reinterpret_cast<const ulonglong2*>(&esb[0 * 100 + q * 4]);
            ulonglong2 h1 = *reinterpret_cast<const ulonglong2*>(&esb[1 * 100 + q * 4]);
            ulonglong2 h2 = *reinterpret_cast<const ulonglong2*>(&esb[2 * 100 + q * 4]);
            ulonglong2 h3 = *reinterpret_cast<const ulonglong2*>(&esb[3 * 100 + q * 4]);
            FMA2(acc0, w[2 * q], h0.x);  FMA2(acc0, w[2 * q + 1], h0.y);
            FMA2(acc1, w[2 * q], h1.x);  FMA2(acc1, w[2 * q + 1], h1.y);
            FMA2(acc2, w[2 * q], h2.x);  FMA2(acc2, w[2 * q + 1], h2.y);
            FMA2(acc3, w[2 * q], h3.x);  FMA2(acc3, w[2 * q + 1], h3.y);
        }
        ull accs[4] = {acc0, acc1, acc2, acc3};
        int v0 = c * 4;
#pragma unroll
        for (int r = 0; r < 4; r++) {
            if (v0 + r < V) {
                float lo, hi; unpack2(accs[r], lo, hi);
                g_P[(size_t)(v0 + r) * 256 + slot] = lo + hi + bias;
            }
        }

        // stage prefetched chunk into the other buffer, then one barrier
        if (cn < nchunk) {
            es[buf ^ 1][j] = r0;
            if (j + 256 < 400) es[buf ^ 1][j + 256] = r1;
        }
        __syncthreads();
        buf ^= 1;
    }
}

// ---------------------------------------------------------------------------
// Kernel 2: fused 2-layer LSTM scan — BYTE-IDENTICAL to the R8 kernel
// (467us best): layer-1 pipelined one step behind; peeled prologue/epilogue;
// branchless interior; quad-remapped gates; cells intra-warp via sact smem.
// DO NOT PERTURB: any interior change tips ptxas 252 -> 255 regs (R9-R12).
// ---------------------------------------------------------------------------
__global__ __launch_bounds__(256, 1)
void scan_kernel(const int*   __restrict__ x,
                 const float* __restrict__ w_hh0,
                 const float* __restrict__ w_ih1,
                 const float* __restrict__ w_hh1,
                 const float* __restrict__ b_ih1,
                 const float* __restrict__ b_hh1,
                 const float* __restrict__ fc_w,
                 const float* __restrict__ fc_b,
                 float* __restrict__ out,
                 int T)
{
    const int HH = 64;
    const int t_ = threadIdx.x;
    const int p  = t_ & 3;        // gate type 0=i 1=f 2=g 3=o
    const int u  = t_ >> 2;       // unit 0..63
    const int r  = p * 64 + u;    // original gate row
    const int b0 = blockIdx.x * 2;
    const bool is_g = (p == 2);

    __shared__ __align__(16) float hs[2][4][68];     // [buf][vec][unit], padded
    __shared__ __align__(16) float sact[4][260];     // [vec][slot 4u+p], padded
    __shared__ int sx[2][512];

    ull w0[32], wi[32], wh[32];
    {
        const ull* q0 = reinterpret_cast<const ull*>(w_hh0 + (size_t)r * HH);
        const ull* q1 = reinterpret_cast<const ull*>(w_ih1 + (size_t)r * HH);
        const ull* q2 = reinterpret_cast<const ull*>(w_hh1 + (size_t)r * HH);
#pragma unroll
        for (int k = 0; k < 32; k++) { w0[k] = q0[k]; wi[k] = q1[k]; wh[k] = q2[k]; }
    }
    const float bias1 = b_ih1[r] + b_hh1[r];

    for (int i = t_; i < T; i += 256) {
        sx[0][i] = x[(size_t)b0 * T + i];
        sx[1][i] = x[(size_t)(b0 + 1) * T + i];
    }
    for (int i = t_; i < 2 * 4 * 68; i += 256) ((float*)hs)[i] = 0.f;

    float cstate = 0.f;     // lane's cell state for its (layer,row) = vec p

    // act = 0.5*tanh(0.5*x)+0.5 for sigmoid gates; tanh(x) for the g gate.
    const float argscale = is_g ? 1.f : 0.5f;
    const float resmul   = is_g ? 1.f : 0.5f;
    const float resadd   = is_g ? 0.f : 0.5f;
    const float* csrc = &sact[p][4 * (unsigned)u];
    const int* sx0 = sx[0];
    const int* sx1 = sx[1];

    __syncthreads();

    float curP0 = g_P[(size_t)sx0[0] * 256 + t_];
    float curP1 = g_P[(size_t)sx1[0] * 256 + t_];

    // ================= prologue t = 0: layer0 only =================
    {
        float nP0 = g_P[(size_t)sx0[1] * 256 + t_];
        float nP1 = g_P[(size_t)sx1[1] * 256 + t_];
        sact[0][t_] = fmaf(tanh_approx(curP0 * argscale), resmul, resadd);
        sact[1][t_] = fmaf(tanh_approx(curP1 * argscale), resmul, resadd);
        __syncwarp();
        if (p < 2) {
            float4 g4 = *reinterpret_cast<const float4*>(csrc);
            cstate = g4.y * cstate + g4.x * g4.z;
            hs[1][p][u] = g4.w * tanh_approx(cstate);
        }
        curP0 = nP0; curP1 = nP1;
        __syncthreads();
    }

    // ================= interior t = 1 .. T-1: rolled, branchless ==========
#pragma unroll 1
    for (int t = 1; t < T; t++) {
        int cur = t & 1, nxt = cur ^ 1;
        int tn = (t + 1 == T) ? 0 : (t + 1);          // uniform select
        float nP0 = g_P[(size_t)sx0[tn] * 256 + t_];
        float nP1 = g_P[(size_t)sx1[tn] * 256 + t_];

        const float* H = &hs[cur][0][0];              // vec rows at stride 68

        ull a0  = pack2(curP0, 0.f);
        ull a1  = pack2(curP1, 0.f);
        ull g1a = pack2(bias1, 0.f);
        ull g1b = pack2(bias1, 0.f);
        ull g1c = 0ull;
        ull g1d = 0ull;
#pragma unroll
        for (int q = 0; q < 16; q++) {
            ulonglong2 u0 = *reinterpret_cast<const ulonglong2*>(H + 0 * 68 + q * 4);
            ulonglong2 u1 = *reinterpret_cast<const ulonglong2*>(H + 1 * 68 + q * 4);
            ulonglong2 v0 = *reinterpret_cast<const ulonglong2*>(H + 2 * 68 + q * 4);
            ulonglong2 v1 = *reinterpret_cast<const ulonglong2*>(H + 3 * 68 + q * 4);
            FMA2(a0,  w0[2 * q],     u0.x);
            FMA2(a1,  w0[2 * q],     u1.x);
            FMA2(g1a, wi[2 * q],     u0.x);
            FMA2(g1b, wi[2 * q],     u1.x);
            FMA2(g1c, wh[2 * q],     v0.x);
            FMA2(g1d, wh[2 * q],     v1.x);
            FMA2(a0,  w0[2 * q + 1], u0.y);
            FMA2(a1,  w0[2 * q + 1], u1.y);
            FMA2(g1a, wi[2 * q + 1], u0.y);
            FMA2(g1b, wi[2 * q + 1], u1.y);
            FMA2(g1c, wh[2 * q + 1], v0.y);
            FMA2(g1d, wh[2 * q + 1], v1.y);
        }
        {
            float lo, hi, lo2, hi2;
            unpack2(a0, lo, hi);  float s0 = lo + hi;
            unpack2(a1, lo, hi);  float s1 = lo + hi;
            unpack2(g1a, lo, hi); unpack2(g1c, lo2, hi2);
            float v0 = (lo + hi) + (lo2 + hi2);
            unpack2(g1b, lo, hi); unpack2(g1d, lo2, hi2);
            float v1 = (lo + hi) + (lo2 + hi2);
            sact[0][t_] = fmaf(tanh_approx(s0 * argscale), resmul, resadd);
            sact[1][t_] = fmaf(tanh_approx(s1 * argscale), resmul, resadd);
            sact[2][t_] = fmaf(tanh_approx(v0 * argscale), resmul, resadd);
            sact[3][t_] = fmaf(tanh_approx(v1 * argscale), resmul, resadd);
        }
        __syncwarp();

        // branchless cell: every lane updates its vec p
        {
            float4 g4 = *reinterpret_cast<const float4*>(csrc);
            cstate = g4.y * cstate + g4.x * g4.z;
            hs[nxt][p][u] = g4.w * tanh_approx(cstate);
        }
        curP0 = nP0; curP1 = nP1;
        __syncthreads();
    }

    // ================= epilogue t = T: layer1 only =================
    {
        const float* H = &hs[T & 1][0][0];
        ull g1a = pack2(bias1, 0.f);
        ull g1b = pack2(bias1, 0.f);
        ull g1c = 0ull;
        ull g1d = 0ull;
#pragma unroll
        for (int q = 0; q < 16; q++) {
            ulonglong2 u0 = *reinterpret_cast<const ulonglong2*>(H + 0 * 68 + q * 4);
            ulonglong2 u1 = *reinterpret_cast<const ulonglong2*>(H + 1 * 68 + q * 4);
            ulonglong2 v0 = *reinterpret_cast<const ulonglong2*>(H + 2 * 68 + q * 4);
            ulonglong2 v1 = *reinterpret_cast<const ulonglong2*>(H + 3 * 68 + q * 4);
            FMA2(g1a, wi[2 * q],     u0.x);
            FMA2(g1b, wi[2 * q],     u1.x);
            FMA2(g1c, wh[2 * q],     v0.x);
            FMA2(g1d, wh[2 * q],     v1.x);
            FMA2(g1a, wi[2 * q + 1], u0.y);
            FMA2(g1b, wi[2 * q + 1], u1.y);
            FMA2(g1c, wh[2 * q + 1], v0.y);
            FMA2(g1d, wh[2 * q + 1], v1.y);
        }
        {
            float lo, hi, lo2, hi2;
            unpack2(g1a, lo, hi); unpack2(g1c, lo2, hi2);
            float v0 = (lo + hi) + (lo2 + hi2);
            unpack2(g1b, lo, hi); unpack2(g1d, lo2, hi2);
            float v1 = (lo + hi) + (lo2 + hi2);
            sact[2][t_] = fmaf(tanh_approx(v0 * argscale), resmul, resadd);
            sact[3][t_] = fmaf(tanh_approx(v1 * argscale), resmul, resadd);
        }
        __syncwarp();
        if (p >= 2) {
            float4 g4 = *reinterpret_cast<const float4*>(csrc);
            cstate = g4.y * cstate + g4.x * g4.z;
            hs[1][p][u] = g4.w * tanh_approx(cstate);   // h1(T-1), buf 1 (T even)
        }
        __syncthreads();
    }

    // ---- final: out[b] = sigmoid(relu(h1(T-1)) . fc_w + fc_b) ----
    if (t_ < 2) {
        const float* hf = &hs[1][2 + t_][0];
        float sacc = fc_b[0];
#pragma unroll
        for (int uu = 0; uu < HH; uu++)
            sacc += fmaxf(hf[uu], 0.f) * fc_w[uu];
        out[b0 + t_] = sigf(sacc);
    }
}

// ---------------------------------------------------------------------------
// Launch
// ---------------------------------------------------------------------------
extern "C" void kernel_launch(void* const* d_in, const int* in_sizes, int n_in,
                              void* d_out, int out_size)
{
    const int*   x     = (const int*)  d_in[0];
    const float* emb   = (const float*)d_in[1];
    const float* w_ih0 = (const float*)d_in[2];
    const float* w_hh0 = (const float*)d_in[3];
    const float* b_ih0 = (const float*)d_in[4];
    const float* b_hh0 = (const float*)d_in[5];
    const float* w_ih1 = (const float*)d_in[6];
    const float* w_hh1 = (const float*)d_in[7];
    const float* b_ih1 = (const float*)d_in[8];
    const float* b_hh1 = (const float*)d_in[9];
    const float* fc_w  = (const float*)d_in[10];
    const float* fc_b  = (const float*)d_in[11];
    float* out = (float*)d_out;

    const int B = out_size;              // 256
    const int T = in_sizes[0] / B;       // 512 (even)
    const int E = in_sizes[2] / 256;     // 100
    const int V = in_sizes[1] / E;       // 50000

    (void)n_in; (void)E;

    prep_kernel<<<296, 256>>>(emb, w_ih0, b_ih0, b_hh0, V);
    scan_kernel<<<B / 2, 256>>>(x, w_hh0, w_ih1, w_hh1, b_ih1, b_hh1,
                                fc_w, fc_b, out, T);
}

// round 14
// speedup vs baseline: 1.1753x; 1.0126x over previous
#include <cuda_runtime.h>
#include <cstdint>

typedef unsigned long long ull;

__device__ __forceinline__ ull pack2(float lo, float hi) {
    ull r; asm("mov.b64 %0, {%1, %2};" : "=l"(r) : "f"(lo), "f"(hi)); return r;
}
__device__ __forceinline__ void unpack2(ull v, float& lo, float& hi) {
    asm("mov.b64 {%0, %1}, %2;" : "=f"(lo), "=f"(hi) : "l"(v));
}
#define FMA2(acc, a, b) asm("fma.rn.f32x2 %0, %1, %2, %0;" : "+l"(acc) : "l"(a), "l"(b))

__device__ __forceinline__ float tanh_approx(float x) {
    float y; asm("tanh.approx.f32 %0, %1;" : "=f"(y) : "f"(x)); return y;
}
__device__ __forceinline__ float sigf(float x) {           // final output only
    return __fdividef(1.f, 1.f + __expf(-x));
}

// P[v][slot], slot-permuted: slot 4u+p holds gate row p*64+u.  (51.2 MB)
__device__ float g_P[50000 * 256];

// ---------------------------------------------------------------------------
// Kernel 1 (v3): per-vocab input transform, double-buffered smem staging,
// COALESCED writes: thread j owns gate row jj = 64*(j&3) + (j>>2), whose
// permuted slot is exactly j -> g_P writes are stride-1 STG.32.
// ---------------------------------------------------------------------------
__global__ __launch_bounds__(256, 2)
void prep_kernel(const float* __restrict__ emb,
                 const float* __restrict__ w_ih0,
                 const float* __restrict__ b_ih0,
                 const float* __restrict__ b_hh0,
                 int V)
{
    const int E = 100;
    const int j  = threadIdx.x;
    const int jj = 64 * (j & 3) + (j >> 2);      // inverse-permuted gate row

    ull w[50];
    {
        const ull* wp = reinterpret_cast<const ull*>(w_ih0 + (size_t)jj * E);
#pragma unroll
        for (int k = 0; k < 50; k++) w[k] = wp[k];
    }
    const float bias = b_ih0[jj] + b_hh0[jj];

    __shared__ __align__(16) float es[2][400];

    const int nchunk = (V + 3) / 4;              // 12500 for V=50000
    int c = blockIdx.x;
    if (c >= nchunk) return;

    // prologue: stage chunk c into es[0]
    {
        const float* base = emb + (size_t)c * 400;
        es[0][j] = base[j];
        int j2 = j + 256;
        if (j2 < 400) es[0][j2] = base[j2];
    }
    __syncthreads();

    int buf = 0;
    for (; c < nchunk; c += gridDim.x) {
        int cn = c + gridDim.x;
        // prefetch next chunk into registers (LDG in flight across compute)
        float r0 = 0.f, r1 = 0.f;
        if (cn < nchunk) {
            const float* base = emb + (size_t)cn * 400;
            r0 = base[j];
            if (j + 256 < 400) r1 = base[j + 256];
        }

        const float* esb = es[buf];
        ull acc0 = 0, acc1 = 0, acc2 = 0, acc3 = 0;
#pragma unroll
        for (int q = 0; q < 25; q++) {
            ulonglong2 h0 = *reinterpret_cast<const ulonglong2*>(&esb[0 * 100 + q * 4]);
            ulonglong2 h1 = *reinterpret_cast<const ulonglong2*>(&esb[1 * 100 + q * 4]);
            ulonglong2 h2 = *reinterpret_cast<const ulonglong2*>(&esb[2 * 100 + q * 4]);
            ulonglong2 h3 = *reinterpret_cast<const ulonglong2*>(&esb[3 * 100 + q * 4]);
            FMA2(acc0, w[2 * q], h0.x);  FMA2(acc0, w[2 * q + 1], h0.y);
            FMA2(acc1, w[2 * q], h1.x);  FMA2(acc1, w[2 * q + 1], h1.y);
            FMA2(acc2, w[2 * q], h2.x);  FMA2(acc2, w[2 * q + 1], h2.y);
            FMA2(acc3, w[2 * q], h3.x);  FMA2(acc3, w[2 * q + 1], h3.y);
        }
        ull accs[4] = {acc0, acc1, acc2, acc3};
        int v0 = c * 4;
#pragma unroll
        for (int r = 0; r < 4; r++) {
            if (v0 + r < V) {
                float lo, hi; unpack2(accs[r], lo, hi);
                g_P[(size_t)(v0 + r) * 256 + j] = lo + hi + bias;   // coalesced
            }
        }

        // stage prefetched chunk into the other buffer, then one barrier
        if (cn < nchunk) {
            es[buf ^ 1][j] = r0;
            if (j + 256 < 400) es[buf ^ 1][j + 256] = r1;
        }
        __syncthreads();
        buf ^= 1;
    }
}

// ---------------------------------------------------------------------------
// Kernel 2: fused 2-layer LSTM scan — BYTE-IDENTICAL to the R8/R13 kernel
// (412us, 252 regs): layer-1 pipelined one step behind; peeled prologue/
// epilogue; branchless interior; quad-remapped gates; intra-warp cells.
// DO NOT PERTURB: any interior change tips ptxas 252 -> 255 regs (R9-R12).
// ---------------------------------------------------------------------------
__global__ __launch_bounds__(256, 1)
void scan_kernel(const int*   __restrict__ x,
                 const float* __restrict__ w_hh0,
                 const float* __restrict__ w_ih1,
                 const float* __restrict__ w_hh1,
                 const float* __restrict__ b_ih1,
                 const float* __restrict__ b_hh1,
                 const float* __restrict__ fc_w,
                 const float* __restrict__ fc_b,
                 float* __restrict__ out,
                 int T)
{
    const int HH = 64;
    const int t_ = threadIdx.x;
    const int p  = t_ & 3;        // gate type 0=i 1=f 2=g 3=o
    const int u  = t_ >> 2;       // unit 0..63
    const int r  = p * 64 + u;    // original gate row
    const int b0 = blockIdx.x * 2;
    const bool is_g = (p == 2);

    __shared__ __align__(16) float hs[2][4][68];     // [buf][vec][unit], padded
    __shared__ __align__(16) float sact[4][260];     // [vec][slot 4u+p], padded
    __shared__ int sx[2][512];

    ull w0[32], wi[32], wh[32];
    {
        const ull* q0 = reinterpret_cast<const ull*>(w_hh0 + (size_t)r * HH);
        const ull* q1 = reinterpret_cast<const ull*>(w_ih1 + (size_t)r * HH);
        const ull* q2 = reinterpret_cast<const ull*>(w_hh1 + (size_t)r * HH);
#pragma unroll
        for (int k = 0; k < 32; k++) { w0[k] = q0[k]; wi[k] = q1[k]; wh[k] = q2[k]; }
    }
    const float bias1 = b_ih1[r] + b_hh1[r];

    for (int i = t_; i < T; i += 256) {
        sx[0][i] = x[(size_t)b0 * T + i];
        sx[1][i] = x[(size_t)(b0 + 1) * T + i];
    }
    for (int i = t_; i < 2 * 4 * 68; i += 256) ((float*)hs)[i] = 0.f;

    float cstate = 0.f;     // lane's cell state for its (layer,row) = vec p

    // act = 0.5*tanh(0.5*x)+0.5 for sigmoid gates; tanh(x) for the g gate.
    const float argscale = is_g ? 1.f : 0.5f;
    const float resmul   = is_g ? 1.f : 0.5f;
    const float resadd   = is_g ? 0.f : 0.5f;
    const float* csrc = &sact[p][4 * (unsigned)u];
    const int* sx0 = sx[0];
    const int* sx1 = sx[1];

    __syncthreads();

    float curP0 = g_P[(size_t)sx0[0] * 256 + t_];
    float curP1 = g_P[(size_t)sx1[0] * 256 + t_];

    // ================= prologue t = 0: layer0 only =================
    {
        float nP0 = g_P[(size_t)sx0[1] * 256 + t_];
        float nP1 = g_P[(size_t)sx1[1] * 256 + t_];
        sact[0][t_] = fmaf(tanh_approx(curP0 * argscale), resmul, resadd);
        sact[1][t_] = fmaf(tanh_approx(curP1 * argscale), resmul, resadd);
        __syncwarp();
        if (p < 2) {
            float4 g4 = *reinterpret_cast<const float4*>(csrc);
            cstate = g4.y * cstate + g4.x * g4.z;
            hs[1][p][u] = g4.w * tanh_approx(cstate);
        }
        curP0 = nP0; curP1 = nP1;
        __syncthreads();
    }

    // ================= interior t = 1 .. T-1: rolled, branchless ==========
#pragma unroll 1
    for (int t = 1; t < T; t++) {
        int cur = t & 1, nxt = cur ^ 1;
        int tn = (t + 1 == T) ? 0 : (t + 1);          // uniform select
        float nP0 = g_P[(size_t)sx0[tn] * 256 + t_];
        float nP1 = g_P[(size_t)sx1[tn] * 256 + t_];

        const float* H = &hs[cur][0][0];              // vec rows at stride 68

        ull a0  = pack2(curP0, 0.f);
        ull a1  = pack2(curP1, 0.f);
        ull g1a = pack2(bias1, 0.f);
        ull g1b = pack2(bias1, 0.f);
        ull g1c = 0ull;
        ull g1d = 0ull;
#pragma unroll
        for (int q = 0; q < 16; q++) {
            ulonglong2 u0 = *reinterpret_cast<const ulonglong2*>(H + 0 * 68 + q * 4);
            ulonglong2 u1 = *reinterpret_cast<const ulonglong2*>(H + 1 * 68 + q * 4);
            ulonglong2 v0 = *reinterpret_cast<const ulonglong2*>(H + 2 * 68 + q * 4);
            ulonglong2 v1 = *reinterpret_cast<const ulonglong2*>(H + 3 * 68 + q * 4);
            FMA2(a0,  w0[2 * q],     u0.x);
            FMA2(a1,  w0[2 * q],     u1.x);
            FMA2(g1a, wi[2 * q],     u0.x);
            FMA2(g1b, wi[2 * q],     u1.x);
            FMA2(g1c, wh[2 * q],     v0.x);
            FMA2(g1d, wh[2 * q],     v1.x);
            FMA2(a0,  w0[2 * q + 1], u0.y);
            FMA2(a1,  w0[2 * q + 1], u1.y);
            FMA2(g1a, wi[2 * q + 1], u0.y);
            FMA2(g1b, wi[2 * q + 1], u1.y);
            FMA2(g1c, wh[2 * q + 1], v0.y);
            FMA2(g1d, wh[2 * q + 1], v1.y);
        }
        {
            float lo, hi, lo2, hi2;
            unpack2(a0, lo, hi);  float s0 = lo + hi;
            unpack2(a1, lo, hi);  float s1 = lo + hi;
            unpack2(g1a, lo, hi); unpack2(g1c, lo2, hi2);
            float v0 = (lo + hi) + (lo2 + hi2);
            unpack2(g1b, lo, hi); unpack2(g1d, lo2, hi2);
            float v1 = (lo + hi) + (lo2 + hi2);
            sact[0][t_] = fmaf(tanh_approx(s0 * argscale), resmul, resadd);
            sact[1][t_] = fmaf(tanh_approx(s1 * argscale), resmul, resadd);
            sact[2][t_] = fmaf(tanh_approx(v0 * argscale), resmul, resadd);
            sact[3][t_] = fmaf(tanh_approx(v1 * argscale), resmul, resadd);
        }
        __syncwarp();

        // branchless cell: every lane updates its vec p
        {
            float4 g4 = *reinterpret_cast<const float4*>(csrc);
            cstate = g4.y * cstate + g4.x * g4.z;
            hs[nxt][p][u] = g4.w * tanh_approx(cstate);
        }
        curP0 = nP0; curP1 = nP1;
        __syncthreads();
    }

    // ================= epilogue t = T: layer1 only =================
    {
        const float* H = &hs[T & 1][0][0];
        ull g1a = pack2(bias1, 0.f);
        ull g1b = pack2(bias1, 0.f);
        ull g1c = 0ull;
        ull g1d = 0ull;
#pragma unroll
        for (int q = 0; q < 16; q++) {
            ulonglong2 u0 = *reinterpret_cast<const ulonglong2*>(H + 0 * 68 + q * 4);
            ulonglong2 u1 = *reinterpret_cast<const ulonglong2*>(H + 1 * 68 + q * 4);
            ulonglong2 v0 = *reinterpret_cast<const ulonglong2*>(H + 2 * 68 + q * 4);
            ulonglong2 v1 = *reinterpret_cast<const ulonglong2*>(H + 3 * 68 + q * 4);
            FMA2(g1a, wi[2 * q],     u0.x);
            FMA2(g1b, wi[2 * q],     u1.x);
            FMA2(g1c, wh[2 * q],     v0.x);
            FMA2(g1d, wh[2 * q],     v1.x);
            FMA2(g1a, wi[2 * q + 1], u0.y);
            FMA2(g1b, wi[2 * q + 1], u1.y);
            FMA2(g1c, wh[2 * q + 1], v0.y);
            FMA2(g1d, wh[2 * q + 1], v1.y);
        }
        {
            float lo, hi, lo2, hi2;
            unpack2(g1a, lo, hi); unpack2(g1c, lo2, hi2);
            float v0 = (lo + hi) + (lo2 + hi2);
            unpack2(g1b, lo, hi); unpack2(g1d, lo2, hi2);
            float v1 = (lo + hi) + (lo2 + hi2);
            sact[2][t_] = fmaf(tanh_approx(v0 * argscale), resmul, resadd);
            sact[3][t_] = fmaf(tanh_approx(v1 * argscale), resmul, resadd);
        }
        __syncwarp();
        if (p >= 2) {
            float4 g4 = *reinterpret_cast<const float4*>(csrc);
            cstate = g4.y * cstate + g4.x * g4.z;
            hs[1][p][u] = g4.w * tanh_approx(cstate);   // h1(T-1), buf 1 (T even)
        }
        __syncthreads();
    }

    // ---- final: out[b] = sigmoid(relu(h1(T-1)) . fc_w + fc_b) ----
    if (t_ < 2) {
        const float* hf = &hs[1][2 + t_][0];
        float sacc = fc_b[0];
#pragma unroll
        for (int uu = 0; uu < HH; uu++)
            sacc += fmaxf(hf[uu], 0.f) * fc_w[uu];
        out[b0 + t_] = sigf(sacc);
    }
}

// ---------------------------------------------------------------------------
// Launch
// ---------------------------------------------------------------------------
extern "C" void kernel_launch(void* const* d_in, const int* in_sizes, int n_in,
                              void* d_out, int out_size)
{
    const int*   x     = (const int*)  d_in[0];
    const float* emb   = (const float*)d_in[1];
    const float* w_ih0 = (const float*)d_in[2];
    const float* w_hh0 = (const float*)d_in[3];
    const float* b_ih0 = (const float*)d_in[4];
    const float* b_hh0 = (const float*)d_in[5];
    const float* w_ih1 = (const float*)d_in[6];
    const float* w_hh1 = (const float*)d_in[7];
    const float* b_ih1 = (const float*)d_in[8];
    const float* b_hh1 = (const float*)d_in[9];
    const float* fc_w  = (const float*)d_in[10];
    const float* fc_b  = (const float*)d_in[11];
    float* out = (float*)d_out;

    const int B = out_size;              // 256
    const int T = in_sizes[0] / B;       // 512 (even)
    const int E = in_sizes[2] / 256;     // 100
    const int V = in_sizes[1] / E;       // 50000

    (void)n_in; (void)E;

    prep_kernel<<<296, 256>>>(emb, w_ih0, b_ih0, b_hh0, V);
    scan_kernel<<<B / 2, 256>>>(x, w_hh0, w_ih1, w_hh1, b_ih1, b_hh1,
                                fc_w, fc_b, out, T);
}

// round 16
// speedup vs baseline: 1.1806x; 1.0045x over previous
#include <cuda_runtime.h>
#include <cuda_bf16.h>
#include <cstdint>

typedef unsigned long long ull;

__device__ __forceinline__ ull pack2(float lo, float hi) {
    ull r; asm("mov.b64 %0, {%1, %2};" : "=l"(r) : "f"(lo), "f"(hi)); return r;
}
__device__ __forceinline__ void unpack2(ull v, float& lo, float& hi) {
    asm("mov.b64 {%0, %1}, %2;" : "=f"(lo), "=f"(hi) : "l"(v));
}
#define FMA2(acc, a, b) asm("fma.rn.f32x2 %0, %1, %2, %0;" : "+l"(acc) : "l"(a), "l"(b))

__device__ __forceinline__ float tanh_approx(float x) {
    float y; asm("tanh.approx.f32 %0, %1;" : "=f"(y) : "f"(x)); return y;
}
__device__ __forceinline__ float sigf(float x) {           // final output only
    return __fdividef(1.f, 1.f + __expf(-x));
}

// P[v][slot], slot-permuted: slot 4u+p holds gate row p*64+u.  (51.2 MB)
__device__ float g_P[50000 * 256];

// ===========================================================================
// Prep via classic HMMA (mma.sync m16n8k16 bf16, sm_80 baseline PTX — the
// harness targets plain sm_103, which rejects tcgen05 but accepts this).
// ===========================================================================
#define MMA16816(d, a0, a1, a2, a3, b0, b1)                                   \
    asm volatile("mma.sync.aligned.m16n8k16.row.col.f32.bf16.bf16.f32 "       \
        "{%0,%1,%2,%3}, {%4,%5,%6,%7}, {%8,%9}, {%0,%1,%2,%3};"               \
        : "+f"((d)[0]), "+f"((d)[1]), "+f"((d)[2]), "+f"((d)[3])              \
        : "r"(a0), "r"(a1), "r"(a2), "r"(a3), "r"(b0), "r"(b1))

__device__ __forceinline__ void cvt_hilo(float f0, float f1,
                                         uint32_t& hi, uint32_t& lo) {
    __nv_bfloat16 h0 = __float2bfloat16(f0), h1 = __float2bfloat16(f1);
    float r0 = f0 - __bfloat162float(h0);
    float r1 = f1 - __bfloat162float(h1);
    __nv_bfloat16 l0 = __float2bfloat16(r0), l1 = __float2bfloat16(r1);
    hi = ((uint32_t)__bfloat16_as_ushort(h1) << 16) | __bfloat16_as_ushort(h0);
    lo = ((uint32_t)__bfloat16_as_ushort(l1) << 16) | __bfloat16_as_ushort(l0);
}

// SMEM (uint32 granules, row stride 60 = 120 bf16, conflict-free frag LDS):
//   A_hi [128][60] @0      A_lo @7680     B_hi [256][60] @15360   B_lo @30720
#define PM_AHI 0
#define PM_ALO 7680
#define PM_BHI 15360
#define PM_BLO 30720
#define PM_SMEM_U32 46080
#define PM_SMEM_BYTES (PM_SMEM_U32 * 4)   // 184320

__global__ __launch_bounds__(256, 1)
void prep_mma(const float* __restrict__ emb,
              const float* __restrict__ w_ih0,
              const float* __restrict__ b_ih0,
              const float* __restrict__ b_hh0,
              int V)
{
    extern __shared__ __align__(16) uint32_t sm[];
    const int tid  = threadIdx.x;
    const int warp = tid >> 5;
    const int lane = tid & 31;
    const int g    = lane >> 2;     // group row 0..7
    const int t    = lane & 3;      // thread-in-group 0..3

    const int v0 = blockIdx.x * 128;
    const int nvalid = min(128, V - v0);
    if (nvalid <= 0) return;

    // ---- zero all smem (covers K-pad 100..111 and short A tiles) ----
    for (int i = tid; i < PM_SMEM_U32 / 4; i += 256)
        reinterpret_cast<uint4*>(sm)[i] = make_uint4(0, 0, 0, 0);
    __syncthreads();

    // ---- stage B (permuted rows): smem row s <- weight row 64*(s&3)+(s>>2)
    {
        int s = tid;                               // 0..255
        int n = 64 * (s & 3) + (s >> 2);
        const float* src = w_ih0 + (size_t)n * 100;
#pragma unroll 1
        for (int cp = 0; cp < 50; cp++) {
            float2 f = reinterpret_cast<const float2*>(src)[cp];
            uint32_t hi, lo;
            cvt_hilo(f.x, f.y, hi, lo);
            sm[PM_BHI + s * 60 + cp] = hi;
            sm[PM_BLO + s * 60 + cp] = lo;
        }
    }

    // ---- stage A tile: nvalid rows x 50 col-pairs ----
    {
        int npairs = nvalid * 50;
#pragma unroll 1
        for (int i = tid; i < npairs; i += 256) {
            int row = i / 50, cp = i - row * 50;
            float2 f = reinterpret_cast<const float2*>(
                           emb + (size_t)(v0 + row) * 100)[cp];
            uint32_t hi, lo;
            cvt_hilo(f.x, f.y, hi, lo);
            sm[PM_AHI + row * 60 + cp] = hi;
            sm[PM_ALO + row * 60 + cp] = lo;
        }
    }

    // ---- per-lane biases for its 8 output columns ----
    float biasv[8];
#pragma unroll
    for (int nt = 0; nt < 4; nt++) {
        int c0 = warp * 32 + nt * 8 + 2 * t;
        int n0 = 64 * (c0 & 3) + (c0 >> 2);
        int c1 = c0 + 1;
        int n1 = 64 * (c1 & 3) + (c1 >> 2);
        biasv[2 * nt]     = b_ih0[n0] + b_hh0[n0];
        biasv[2 * nt + 1] = b_ih0[n1] + b_hh0[n1];
    }
    __syncthreads();

    // ---- MMA: 8 m-tiles x 4 n-tiles x 7 k-steps x 3 passes ----
#pragma unroll 1
    for (int m = 0; m < 8; m++) {
        const int m0 = m * 16;
        float acc[4][4];
#pragma unroll
        for (int nt = 0; nt < 4; nt++) {
            acc[nt][0] = biasv[2 * nt];
            acc[nt][1] = biasv[2 * nt + 1];
            acc[nt][2] = biasv[2 * nt];
            acc[nt][3] = biasv[2 * nt + 1];
        }
#pragma unroll
        for (int k = 0; k < 7; k++) {
            const int kc = k * 8 + t;            // granule index within row
            const int ra = (m0 + g) * 60 + kc;
            const int rb = (m0 + g + 8) * 60 + kc;
            uint32_t ah0 = sm[PM_AHI + ra];
            uint32_t ah1 = sm[PM_AHI + rb];
            uint32_t ah2 = sm[PM_AHI + ra + 4];
            uint32_t ah3 = sm[PM_AHI + rb + 4];
            uint32_t al0 = sm[PM_ALO + ra];
            uint32_t al1 = sm[PM_ALO + rb];
            uint32_t al2 = sm[PM_ALO + ra + 4];
            uint32_t al3 = sm[PM_ALO + rb + 4];
#pragma unroll
            for (int nt = 0; nt < 4; nt++) {
                int srow = (warp * 32 + nt * 8 + g) * 60 + kc;
                uint32_t bh0 = sm[PM_BHI + srow];
                uint32_t bh1 = sm[PM_BHI + srow + 4];
                uint32_t bl0 = sm[PM_BLO + srow];
                uint32_t bl1 = sm[PM_BLO + srow + 4];
                MMA16816(acc[nt], ah0, ah1, ah2, ah3, bh0, bh1);
                MMA16816(acc[nt], ah0, ah1, ah2, ah3, bl0, bl1);
                MMA16816(acc[nt], al0, al1, al2, al3, bh0, bh1);
            }
        }
        // ---- store: D rows v0+m0+g and +8; cols already slot-indexed ----
        int vlo = v0 + m0 + g;
        int vhi = vlo + 8;
#pragma unroll
        for (int nt = 0; nt < 4; nt++) {
            int c = warp * 32 + nt * 8 + 2 * t;
            if (vlo < V)
                *reinterpret_cast<float2*>(&g_P[(size_t)vlo * 256 + c]) =
                    make_float2(acc[nt][0], acc[nt][1]);
            if (vhi < V)
                *reinterpret_cast<float2*>(&g_P[(size_t)vhi * 256 + c]) =
                    make_float2(acc[nt][2], acc[nt][3]);
        }
    }
}

// ---------------------------------------------------------------------------
// Kernel 2: fused 2-layer LSTM scan — BYTE-IDENTICAL to the R8/R14 kernel
// (412us, 252 regs). DO NOT PERTURB (R9-R12: any edit -> 255 regs, slower).
// ---------------------------------------------------------------------------
__global__ __launch_bounds__(256, 1)
void scan_kernel(const int*   __restrict__ x,
                 const float* __restrict__ w_hh0,
                 const float* __restrict__ w_ih1,
                 const float* __restrict__ w_hh1,
                 const float* __restrict__ b_ih1,
                 const float* __restrict__ b_hh1,
                 const float* __restrict__ fc_w,
                 const float* __restrict__ fc_b,
                 float* __restrict__ out,
                 int T)
{
    const int HH = 64;
    const int t_ = threadIdx.x;
    const int p  = t_ & 3;        // gate type 0=i 1=f 2=g 3=o
    const int u  = t_ >> 2;       // unit 0..63
    const int r  = p * 64 + u;    // original gate row
    const int b0 = blockIdx.x * 2;
    const bool is_g = (p == 2);

    __shared__ __align__(16) float hs[2][4][68];     // [buf][vec][unit], padded
    __shared__ __align__(16) float sact[4][260];     // [vec][slot 4u+p], padded
    __shared__ int sx[2][512];

    ull w0[32], wi[32], wh[32];
    {
        const ull* q0 = reinterpret_cast<const ull*>(w_hh0 + (size_t)r * HH);
        const ull* q1 = reinterpret_cast<const ull*>(w_ih1 + (size_t)r * HH);
        const ull* q2 = reinterpret_cast<const ull*>(w_hh1 + (size_t)r * HH);
#pragma unroll
        for (int k = 0; k < 32; k++) { w0[k] = q0[k]; wi[k] = q1[k]; wh[k] = q2[k]; }
    }
    const float bias1 = b_ih1[r] + b_hh1[r];

    for (int i = t_; i < T; i += 256) {
        sx[0][i] = x[(size_t)b0 * T + i];
        sx[1][i] = x[(size_t)(b0 + 1) * T + i];
    }
    for (int i = t_; i < 2 * 4 * 68; i += 256) ((float*)hs)[i] = 0.f;

    float cstate = 0.f;     // lane's cell state for its (layer,row) = vec p

    // act = 0.5*tanh(0.5*x)+0.5 for sigmoid gates; tanh(x) for the g gate.
    const float argscale = is_g ? 1.f : 0.5f;
    const float resmul   = is_g ? 1.f : 0.5f;
    const float resadd   = is_g ? 0.f : 0.5f;
    const float* csrc = &sact[p][4 * (unsigned)u];
    const int* sx0 = sx[0];
    const int* sx1 = sx[1];

    __syncthreads();

    float curP0 = g_P[(size_t)sx0[0] * 256 + t_];
    float curP1 = g_P[(size_t)sx1[0] * 256 + t_];

    // ================= prologue t = 0: layer0 only =================
    {
        float nP0 = g_P[(size_t)sx0[1] * 256 + t_];
        float nP1 = g_P[(size_t)sx1[1] * 256 + t_];
        sact[0][t_] = fmaf(tanh_approx(curP0 * argscale), resmul, resadd);
        sact[1][t_] = fmaf(tanh_approx(curP1 * argscale), resmul, resadd);
        __syncwarp();
        if (p < 2) {
            float4 g4 = *reinterpret_cast<const float4*>(csrc);
            cstate = g4.y * cstate + g4.x * g4.z;
            hs[1][p][u] = g4.w * tanh_approx(cstate);
        }
        curP0 = nP0; curP1 = nP1;
        __syncthreads();
    }

    // ================= interior t = 1 .. T-1: rolled, branchless ==========
#pragma unroll 1
    for (int t = 1; t < T; t++) {
        int cur = t & 1, nxt = cur ^ 1;
        int tn = (t + 1 == T) ? 0 : (t + 1);          // uniform select
        float nP0 = g_P[(size_t)sx0[tn] * 256 + t_];
        float nP1 = g_P[(size_t)sx1[tn] * 256 + t_];

        const float* H = &hs[cur][0][0];              // vec rows at stride 68

        ull a0  = pack2(curP0, 0.f);
        ull a1  = pack2(curP1, 0.f);
        ull g1a = pack2(bias1, 0.f);
        ull g1b = pack2(bias1, 0.f);
        ull g1c = 0ull;
        ull g1d = 0ull;
#pragma unroll
        for (int q = 0; q < 16; q++) {
            ulonglong2 u0 = *reinterpret_cast<const ulonglong2*>(H + 0 * 68 + q * 4);
            ulonglong2 u1 = *reinterpret_cast<const ulonglong2*>(H + 1 * 68 + q * 4);
            ulonglong2 v0 = *reinterpret_cast<const ulonglong2*>(H + 2 * 68 + q * 4);
            ulonglong2 v1 = *reinterpret_cast<const ulonglong2*>(H + 3 * 68 + q * 4);
            FMA2(a0,  w0[2 * q],     u0.x);
            FMA2(a1,  w0[2 * q],     u1.x);
            FMA2(g1a, wi[2 * q],     u0.x);
            FMA2(g1b, wi[2 * q],     u1.x);
            FMA2(g1c, wh[2 * q],     v0.x);
            FMA2(g1d, wh[2 * q],     v1.x);
            FMA2(a0,  w0[2 * q + 1], u0.y);
            FMA2(a1,  w0[2 * q + 1], u1.y);
            FMA2(g1a, wi[2 * q + 1], u0.y);
            FMA2(g1b, wi[2 * q + 1], u1.y);
            FMA2(g1c, wh[2 * q + 1], v0.y);
            FMA2(g1d, wh[2 * q + 1], v1.y);
        }
        {
            float lo, hi, lo2, hi2;
            unpack2(a0, lo, hi);  float s0 = lo + hi;
            unpack2(a1, lo, hi);  float s1 = lo + hi;
            unpack2(g1a, lo, hi); unpack2(g1c, lo2, hi2);
            float v0 = (lo + hi) + (lo2 + hi2);
            unpack2(g1b, lo, hi); unpack2(g1d, lo2, hi2);
            float v1 = (lo + hi) + (lo2 + hi2);
            sact[0][t_] = fmaf(tanh_approx(s0 * argscale), resmul, resadd);
            sact[1][t_] = fmaf(tanh_approx(s1 * argscale), resmul, resadd);
            sact[2][t_] = fmaf(tanh_approx(v0 * argscale), resmul, resadd);
            sact[3][t_] = fmaf(tanh_approx(v1 * argscale), resmul, resadd);
        }
        __syncwarp();

        // branchless cell: every lane updates its vec p
        {
            float4 g4 = *reinterpret_cast<const float4*>(csrc);
            cstate = g4.y * cstate + g4.x * g4.z;
            hs[nxt][p][u] = g4.w * tanh_approx(cstate);
        }
        curP0 = nP0; curP1 = nP1;
        __syncthreads();
    }

    // ================= epilogue t = T: layer1 only =================
    {
        const float* H = &hs[T & 1][0][0];
        ull g1a = pack2(bias1, 0.f);
        ull g1b = pack2(bias1, 0.f);
        ull g1c = 0ull;
        ull g1d = 0ull;
#pragma unroll
        for (int q = 0; q < 16; q++) {
            ulonglong2 u0 = *reinterpret_cast<const ulonglong2*>(H + 0 * 68 + q * 4);
            ulonglong2 u1 = *reinterpret_cast<const ulonglong2*>(H + 1 * 68 + q * 4);
            ulonglong2 v0 = *reinterpret_cast<const ulonglong2*>(H + 2 * 68 + q * 4);
            ulonglong2 v1 = *reinterpret_cast<const ulonglong2*>(H + 3 * 68 + q * 4);
            FMA2(g1a, wi[2 * q],     u0.x);
            FMA2(g1b, wi[2 * q],     u1.x);
            FMA2(g1c, wh[2 * q],     v0.x);
            FMA2(g1d, wh[2 * q],     v1.x);
            FMA2(g1a, wi[2 * q + 1], u0.y);
            FMA2(g1b, wi[2 * q + 1], u1.y);
            FMA2(g1c, wh[2 * q + 1], v0.y);
            FMA2(g1d, wh[2 * q + 1], v1.y);
        }
        {
            float lo, hi, lo2, hi2;
            unpack2(g1a, lo, hi); unpack2(g1c, lo2, hi2);
            float v0 = (lo + hi) + (lo2 + hi2);
            unpack2(g1b, lo, hi); unpack2(g1d, lo2, hi2);
            float v1 = (lo + hi) + (lo2 + hi2);
            sact[2][t_] = fmaf(tanh_approx(v0 * argscale), resmul, resadd);
            sact[3][t_] = fmaf(tanh_approx(v1 * argscale), resmul, resadd);
        }
        __syncwarp();
        if (p >= 2) {
            float4 g4 = *reinterpret_cast<const float4*>(csrc);
            cstate = g4.y * cstate + g4.x * g4.z;
            hs[1][p][u] = g4.w * tanh_approx(cstate);   // h1(T-1), buf 1 (T even)
        }
        __syncthreads();
    }

    // ---- final: out[b] = sigmoid(relu(h1(T-1)) . fc_w + fc_b) ----
    if (t_ < 2) {
        const float* hf = &hs[1][2 + t_][0];
        float sacc = fc_b[0];
#pragma unroll
        for (int uu = 0; uu < HH; uu++)
            sacc += fmaxf(hf[uu], 0.f) * fc_w[uu];
        out[b0 + t_] = sigf(sacc);
    }
}

// ---------------------------------------------------------------------------
// Launch
// ---------------------------------------------------------------------------
extern "C" void kernel_launch(void* const* d_in, const int* in_sizes, int n_in,
                              void* d_out, int out_size)
{
    const int*   x     = (const int*)  d_in[0];
    const float* emb   = (const float*)d_in[1];
    const float* w_ih0 = (const float*)d_in[2];
    const float* w_hh0 = (const float*)d_in[3];
    const float* b_ih0 = (const float*)d_in[4];
    const float* b_hh0 = (const float*)d_in[5];
    const float* w_ih1 = (const float*)d_in[6];
    const float* w_hh1 = (const float*)d_in[7];
    const float* b_ih1 = (const float*)d_in[8];
    const float* b_hh1 = (const float*)d_in[9];
    const float* fc_w  = (const float*)d_in[10];
    const float* fc_b  = (const float*)d_in[11];
    float* out = (float*)d_out;

    const int B = out_size;              // 256
    const int T = in_sizes[0] / B;       // 512 (even)
    const int E = in_sizes[2] / 256;     // 100
    const int V = in_sizes[1] / E;       // 50000

    (void)n_in; (void)E;

    static int smem_set = 0;
    if (!smem_set) {
        cudaFuncSetAttribute(prep_mma,
                             cudaFuncAttributeMaxDynamicSharedMemorySize,
                             PM_SMEM_BYTES);
        smem_set = 1;
    }
    prep_mma<<<(V + 127) / 128, 256, PM_SMEM_BYTES>>>(emb, w_ih0, b_ih0, b_hh0, V);
    scan_kernel<<<B / 2, 256>>>(x, w_hh0, w_ih1, w_hh1, b_ih1, b_hh1,
                                fc_w, fc_b, out, T);
}

// round 17
// speedup vs baseline: 1.2685x; 1.0745x over previous
#include <cuda_runtime.h>
#include <cuda_bf16.h>
#include <cstdint>

typedef unsigned long long ull;

__device__ __forceinline__ ull pack2(float lo, float hi) {
    ull r; asm("mov.b64 %0, {%1, %2};" : "=l"(r) : "f"(lo), "f"(hi)); return r;
}
__device__ __forceinline__ void unpack2(ull v, float& lo, float& hi) {
    asm("mov.b64 {%0, %1}, %2;" : "=f"(lo), "=f"(hi) : "l"(v));
}
#define FMA2(acc, a, b) asm("fma.rn.f32x2 %0, %1, %2, %0;" : "+l"(acc) : "l"(a), "l"(b))

__device__ __forceinline__ float tanh_approx(float x) {
    float y; asm("tanh.approx.f32 %0, %1;" : "=f"(y) : "f"(x)); return y;
}
__device__ __forceinline__ float sigf(float x) {           // final output only
    return __fdividef(1.f, 1.f + __expf(-x));
}

// P[v][slot], slot-permuted: slot 4u+p holds gate row p*64+u.  (51.2 MB)
__device__ float g_P[50000 * 256];

// ===========================================================================
// Prep via classic HMMA (mma.sync m16n8k16 bf16, sm_80 baseline PTX — the
// harness targets plain sm_103, which rejects tcgen05 but accepts this).
// ===========================================================================
#define MMA16816(d, a0, a1, a2, a3, b0, b1)                                   \
    asm volatile("mma.sync.aligned.m16n8k16.row.col.f32.bf16.bf16.f32 "       \
        "{%0,%1,%2,%3}, {%4,%5,%6,%7}, {%8,%9}, {%0,%1,%2,%3};"               \
        : "+f"((d)[0]), "+f"((d)[1]), "+f"((d)[2]), "+f"((d)[3])              \
        : "r"(a0), "r"(a1), "r"(a2), "r"(a3), "r"(b0), "r"(b1))

__device__ __forceinline__ void cvt_hilo(float f0, float f1,
                                         uint32_t& hi, uint32_t& lo) {
    __nv_bfloat16 h0 = __float2bfloat16(f0), h1 = __float2bfloat16(f1);
    float r0 = f0 - __bfloat162float(h0);
    float r1 = f1 - __bfloat162float(h1);
    __nv_bfloat16 l0 = __float2bfloat16(r0), l1 = __float2bfloat16(r1);
    hi = ((uint32_t)__bfloat16_as_ushort(h1) << 16) | __bfloat16_as_ushort(h0);
    lo = ((uint32_t)__bfloat16_as_ushort(l1) << 16) | __bfloat16_as_ushort(l0);
}

// SMEM (uint32 granules, row stride 60 = 120 bf16, conflict-free frag LDS):
//   A_hi [128][60] @0      A_lo @7680     B_hi [256][60] @15360   B_lo @30720
#define PM_AHI 0
#define PM_ALO 7680
#define PM_BHI 15360
#define PM_BLO 30720
#define PM_SMEM_U32 46080
#define PM_SMEM_BYTES (PM_SMEM_U32 * 4)   // 184320

__global__ __launch_bounds__(256, 1)
void prep_mma(const float* __restrict__ emb,
              const float* __restrict__ w_ih0,
              const float* __restrict__ b_ih0,
              const float* __restrict__ b_hh0,
              int V)
{
    extern __shared__ __align__(16) uint32_t sm[];
    const int tid  = threadIdx.x;
    const int warp = tid >> 5;
    const int lane = tid & 31;
    const int g    = lane >> 2;     // group row 0..7
    const int t    = lane & 3;      // thread-in-group 0..3

    const int v0 = blockIdx.x * 128;
    const int nvalid = min(128, V - v0);
    if (nvalid <= 0) return;

    // ---- zero all smem (covers K-pad 100..111 and short A tiles) ----
    for (int i = tid; i < PM_SMEM_U32 / 4; i += 256)
        reinterpret_cast<uint4*>(sm)[i] = make_uint4(0, 0, 0, 0);
    __syncthreads();

    // ---- stage B cooperatively (coalesced, MLP via unroll) ----
    // pair index i over 256 rows x 50 col-pairs; smem row s holds weight
    // row 64*(s&3)+(s>>2) (permutation -> D cols are g_P slots).
#pragma unroll 5
    for (int it = 0; it < 50; it++) {
        int i = it * 256 + tid;
        int s = i / 50, cp = i - s * 50;
        int n = 64 * (s & 3) + (s >> 2);
        float2 f = reinterpret_cast<const float2*>(w_ih0 + (size_t)n * 100)[cp];
        uint32_t hi, lo;
        cvt_hilo(f.x, f.y, hi, lo);
        sm[PM_BHI + s * 60 + cp] = hi;
        sm[PM_BLO + s * 60 + cp] = lo;
    }

    // ---- stage A tile: nvalid rows x 50 col-pairs (MLP via unroll) ----
    {
        int npairs = nvalid * 50;
#pragma unroll 5
        for (int i = tid; i < npairs; i += 256) {
            int row = i / 50, cp = i - row * 50;
            float2 f = reinterpret_cast<const float2*>(
                           emb + (size_t)(v0 + row) * 100)[cp];
            uint32_t hi, lo;
            cvt_hilo(f.x, f.y, hi, lo);
            sm[PM_AHI + row * 60 + cp] = hi;
            sm[PM_ALO + row * 60 + cp] = lo;
        }
    }

    // ---- per-lane biases for its 8 output columns ----
    float biasv[8];
#pragma unroll
    for (int nt = 0; nt < 4; nt++) {
        int c0 = warp * 32 + nt * 8 + 2 * t;
        int n0 = 64 * (c0 & 3) + (c0 >> 2);
        int c1 = c0 + 1;
        int n1 = 64 * (c1 & 3) + (c1 >> 2);
        biasv[2 * nt]     = b_ih0[n0] + b_hh0[n0];
        biasv[2 * nt + 1] = b_ih0[n1] + b_hh0[n1];
    }
    __syncthreads();

    // ---- MMA: 8 m-tiles x 4 n-tiles x 7 k-steps x 3 passes ----
#pragma unroll 1
    for (int m = 0; m < 8; m++) {
        const int m0 = m * 16;
        float acc[4][4];
#pragma unroll
        for (int nt = 0; nt < 4; nt++) {
            acc[nt][0] = biasv[2 * nt];
            acc[nt][1] = biasv[2 * nt + 1];
            acc[nt][2] = biasv[2 * nt];
            acc[nt][3] = biasv[2 * nt + 1];
        }
#pragma unroll
        for (int k = 0; k < 7; k++) {
            const int kc = k * 8 + t;            // granule index within row
            const int ra = (m0 + g) * 60 + kc;
            const int rb = (m0 + g + 8) * 60 + kc;
            uint32_t ah0 = sm[PM_AHI + ra];
            uint32_t ah1 = sm[PM_AHI + rb];
            uint32_t ah2 = sm[PM_AHI + ra + 4];
            uint32_t ah3 = sm[PM_AHI + rb + 4];
            uint32_t al0 = sm[PM_ALO + ra];
            uint32_t al1 = sm[PM_ALO + rb];
            uint32_t al2 = sm[PM_ALO + ra + 4];
            uint32_t al3 = sm[PM_ALO + rb + 4];
#pragma unroll
            for (int nt = 0; nt < 4; nt++) {
                int srow = (warp * 32 + nt * 8 + g) * 60 + kc;
                uint32_t bh0 = sm[PM_BHI + srow];
                uint32_t bh1 = sm[PM_BHI + srow + 4];
                uint32_t bl0 = sm[PM_BLO + srow];
                uint32_t bl1 = sm[PM_BLO + srow + 4];
                MMA16816(acc[nt], ah0, ah1, ah2, ah3, bh0, bh1);
                MMA16816(acc[nt], ah0, ah1, ah2, ah3, bl0, bl1);
                MMA16816(acc[nt], al0, al1, al2, al3, bh0, bh1);
            }
        }
        // ---- store: D rows v0+m0+g and +8; cols already slot-indexed ----
        int vlo = v0 + m0 + g;
        int vhi = vlo + 8;
#pragma unroll
        for (int nt = 0; nt < 4; nt++) {
            int c = warp * 32 + nt * 8 + 2 * t;
            if (vlo < V)
                *reinterpret_cast<float2*>(&g_P[(size_t)vlo * 256 + c]) =
                    make_float2(acc[nt][0], acc[nt][1]);
            if (vhi < V)
                *reinterpret_cast<float2*>(&g_P[(size_t)vhi * 256 + c]) =
                    make_float2(acc[nt][2], acc[nt][3]);
        }
    }
}

// ---------------------------------------------------------------------------
// Kernel 2: fused 2-layer LSTM scan — BYTE-IDENTICAL to the R8/R14 kernel
// (412us, 252 regs). DO NOT PERTURB (R9-R12: any edit -> 255 regs, slower).
// ---------------------------------------------------------------------------
__global__ __launch_bounds__(256, 1)
void scan_kernel(const int*   __restrict__ x,
                 const float* __restrict__ w_hh0,
                 const float* __restrict__ w_ih1,
                 const float* __restrict__ w_hh1,
                 const float* __restrict__ b_ih1,
                 const float* __restrict__ b_hh1,
                 const float* __restrict__ fc_w,
                 const float* __restrict__ fc_b,
                 float* __restrict__ out,
                 int T)
{
    const int HH = 64;
    const int t_ = threadIdx.x;
    const int p  = t_ & 3;        // gate type 0=i 1=f 2=g 3=o
    const int u  = t_ >> 2;       // unit 0..63
    const int r  = p * 64 + u;    // original gate row
    const int b0 = blockIdx.x * 2;
    const bool is_g = (p == 2);

    __shared__ __align__(16) float hs[2][4][68];     // [buf][vec][unit], padded
    __shared__ __align__(16) float sact[4][260];     // [vec][slot 4u+p], padded
    __shared__ int sx[2][512];

    ull w0[32], wi[32], wh[32];
    {
        const ull* q0 = reinterpret_cast<const ull*>(w_hh0 + (size_t)r * HH);
        const ull* q1 = reinterpret_cast<const ull*>(w_ih1 + (size_t)r * HH);
        const ull* q2 = reinterpret_cast<const ull*>(w_hh1 + (size_t)r * HH);
#pragma unroll
        for (int k = 0; k < 32; k++) { w0[k] = q0[k]; wi[k] = q1[k]; wh[k] = q2[k]; }
    }
    const float bias1 = b_ih1[r] + b_hh1[r];

    for (int i = t_; i < T; i += 256) {
        sx[0][i] = x[(size_t)b0 * T + i];
        sx[1][i] = x[(size_t)(b0 + 1) * T + i];
    }
    for (int i = t_; i < 2 * 4 * 68; i += 256) ((float*)hs)[i] = 0.f;

    float cstate = 0.f;     // lane's cell state for its (layer,row) = vec p

    // act = 0.5*tanh(0.5*x)+0.5 for sigmoid gates; tanh(x) for the g gate.
    const float argscale = is_g ? 1.f : 0.5f;
    const float resmul   = is_g ? 1.f : 0.5f;
    const float resadd   = is_g ? 0.f : 0.5f;
    const float* csrc = &sact[p][4 * (unsigned)u];
    const int* sx0 = sx[0];
    const int* sx1 = sx[1];

    __syncthreads();

    float curP0 = g_P[(size_t)sx0[0] * 256 + t_];
    float curP1 = g_P[(size_t)sx1[0] * 256 + t_];

    // ================= prologue t = 0: layer0 only =================
    {
        float nP0 = g_P[(size_t)sx0[1] * 256 + t_];
        float nP1 = g_P[(size_t)sx1[1] * 256 + t_];
        sact[0][t_] = fmaf(tanh_approx(curP0 * argscale), resmul, resadd);
        sact[1][t_] = fmaf(tanh_approx(curP1 * argscale), resmul, resadd);
        __syncwarp();
        if (p < 2) {
            float4 g4 = *reinterpret_cast<const float4*>(csrc);
            cstate = g4.y * cstate + g4.x * g4.z;
            hs[1][p][u] = g4.w * tanh_approx(cstate);
        }
        curP0 = nP0; curP1 = nP1;
        __syncthreads();
    }

    // ================= interior t = 1 .. T-1: rolled, branchless ==========
#pragma unroll 1
    for (int t = 1; t < T; t++) {
        int cur = t & 1, nxt = cur ^ 1;
        int tn = (t + 1 == T) ? 0 : (t + 1);          // uniform select
        float nP0 = g_P[(size_t)sx0[tn] * 256 + t_];
        float nP1 = g_P[(size_t)sx1[tn] * 256 + t_];

        const float* H = &hs[cur][0][0];              // vec rows at stride 68

        ull a0  = pack2(curP0, 0.f);
        ull a1  = pack2(curP1, 0.f);
        ull g1a = pack2(bias1, 0.f);
        ull g1b = pack2(bias1, 0.f);
        ull g1c = 0ull;
        ull g1d = 0ull;
#pragma unroll
        for (int q = 0; q < 16; q++) {
            ulonglong2 u0 = *reinterpret_cast<const ulonglong2*>(H + 0 * 68 + q * 4);
            ulonglong2 u1 = *reinterpret_cast<const ulonglong2*>(H + 1 * 68 + q * 4);
            ulonglong2 v0 = *reinterpret_cast<const ulonglong2*>(H + 2 * 68 + q * 4);
            ulonglong2 v1 = *reinterpret_cast<const ulonglong2*>(H + 3 * 68 + q * 4);
            FMA2(a0,  w0[2 * q],     u0.x);
            FMA2(a1,  w0[2 * q],     u1.x);
            FMA2(g1a, wi[2 * q],     u0.x);
            FMA2(g1b, wi[2 * q],     u1.x);
            FMA2(g1c, wh[2 * q],     v0.x);
            FMA2(g1d, wh[2 * q],     v1.x);
            FMA2(a0,  w0[2 * q + 1], u0.y);
            FMA2(a1,  w0[2 * q + 1], u1.y);
            FMA2(g1a, wi[2 * q + 1], u0.y);
            FMA2(g1b, wi[2 * q + 1], u1.y);
            FMA2(g1c, wh[2 * q + 1], v0.y);
            FMA2(g1d, wh[2 * q + 1], v1.y);
        }
        {
            float lo, hi, lo2, hi2;
            unpack2(a0, lo, hi);  float s0 = lo + hi;
            unpack2(a1, lo, hi);  float s1 = lo + hi;
            unpack2(g1a, lo, hi); unpack2(g1c, lo2, hi2);
            float v0 = (lo + hi) + (lo2 + hi2);
            unpack2(g1b, lo, hi); unpack2(g1d, lo2, hi2);
            float v1 = (lo + hi) + (lo2 + hi2);
            sact[0][t_] = fmaf(tanh_approx(s0 * argscale), resmul, resadd);
            sact[1][t_] = fmaf(tanh_approx(s1 * argscale), resmul, resadd);
            sact[2][t_] = fmaf(tanh_approx(v0 * argscale), resmul, resadd);
            sact[3][t_] = fmaf(tanh_approx(v1 * argscale), resmul, resadd);
        }
        __syncwarp();

        // branchless cell: every lane updates its vec p
        {
            float4 g4 = *reinterpret_cast<const float4*>(csrc);
            cstate = g4.y * cstate + g4.x * g4.z;
            hs[nxt][p][u] = g4.w * tanh_approx(cstate);
        }
        curP0 = nP0; curP1 = nP1;
        __syncthreads();
    }

    // ================= epilogue t = T: layer1 only =================
    {
        const float* H = &hs[T & 1][0][0];
        ull g1a = pack2(bias1, 0.f);
        ull g1b = pack2(bias1, 0.f);
        ull g1c = 0ull;
        ull g1d = 0ull;
#pragma unroll
        for (int q = 0; q < 16; q++) {
            ulonglong2 u0 = *reinterpret_cast<const ulonglong2*>(H + 0 * 68 + q * 4);
            ulonglong2 u1 = *reinterpret_cast<const ulonglong2*>(H + 1 * 68 + q * 4);
            ulonglong2 v0 = *reinterpret_cast<const ulonglong2*>(H + 2 * 68 + q * 4);
            ulonglong2 v1 = *reinterpret_cast<const ulonglong2*>(H + 3 * 68 + q * 4);
            FMA2(g1a, wi[2 * q],     u0.x);
            FMA2(g1b, wi[2 * q],     u1.x);
            FMA2(g1c, wh[2 * q],     v0.x);
            FMA2(g1d, wh[2 * q],     v1.x);
            FMA2(g1a, wi[2 * q + 1], u0.y);
            FMA2(g1b, wi[2 * q + 1], u1.y);
            FMA2(g1c, wh[2 * q + 1], v0.y);
            FMA2(g1d, wh[2 * q + 1], v1.y);
        }
        {
            float lo, hi, lo2, hi2;
            unpack2(g1a, lo, hi); unpack2(g1c, lo2, hi2);
            float v0 = (lo + hi) + (lo2 + hi2);
            unpack2(g1b, lo, hi); unpack2(g1d, lo2, hi2);
            float v1 = (lo + hi) + (lo2 + hi2);
            sact[2][t_] = fmaf(tanh_approx(v0 * argscale), resmul, resadd);
            sact[3][t_] = fmaf(tanh_approx(v1 * argscale), resmul, resadd);
        }
        __syncwarp();
        if (p >= 2) {
            float4 g4 = *reinterpret_cast<const float4*>(csrc);
            cstate = g4.y * cstate + g4.x * g4.z;
            hs[1][p][u] = g4.w * tanh_approx(cstate);   // h1(T-1), buf 1 (T even)
        }
        __syncthreads();
    }

    // ---- final: out[b] = sigmoid(relu(h1(T-1)) . fc_w + fc_b) ----
    if (t_ < 2) {
        const float* hf = &hs[1][2 + t_][0];
        float sacc = fc_b[0];
#pragma unroll
        for (int uu = 0; uu < HH; uu++)
            sacc += fmaxf(hf[uu], 0.f) * fc_w[uu];
        out[b0 + t_] = sigf(sacc);
    }
}

// ---------------------------------------------------------------------------
// Launch
// ---------------------------------------------------------------------------
extern "C" void kernel_launch(void* const* d_in, const int* in_sizes, int n_in,
                              void* d_out, int out_size)
{
    const int*   x     = (const int*)  d_in[0];
    const float* emb   = (const float*)d_in[1];
    const float* w_ih0 = (const float*)d_in[2];
    const float* w_hh0 = (const float*)d_in[3];
    const float* b_ih0 = (const float*)d_in[4];
    const float* b_hh0 = (const float*)d_in[5];
    const float* w_ih1 = (const float*)d_in[6];
    const float* w_hh1 = (const float*)d_in[7];
    const float* b_ih1 = (const float*)d_in[8];
    const float* b_hh1 = (const float*)d_in[9];
    const float* fc_w  = (const float*)d_in[10];
    const float* fc_b  = (const float*)d_in[11];
    float* out = (float*)d_out;

    const int B = out_size;              // 256
    const int T = in_sizes[0] / B;       // 512 (even)
    const int E = in_sizes[2] / 256;     // 100
    const int V = in_sizes[1] / E;       // 50000

    (void)n_in; (void)E;

    static int smem_set = 0;
    if (!smem_set) {
        cudaFuncSetAttribute(prep_mma,
                             cudaFuncAttributeMaxDynamicSharedMemorySize,
                             PM_SMEM_BYTES);
        smem_set = 1;
    }
    prep_mma<<<(V + 127) / 128, 256, PM_SMEM_BYTES>>>(emb, w_ih0, b_ih0, b_hh0, V);
    scan_kernel<<<B / 2, 256>>>(x, w_hh0, w_ih1, w_hh1, b_ih1, b_hh1,
                                fc_w, fc_b, out, T);
}